// round 16
// baseline (speedup 1.0000x reference)
#include <cuda_runtime.h>
#include <cuda_bf16.h>
#include <cuda_fp16.h>
#include <stdint.h>

// ===========================================================================
// Problem constants
// ===========================================================================
namespace {
constexpr int B_    = 16;
constexpr int N_    = 2048;
constexpr int H_    = 256;
constexpr int KOUT_ = 128;
constexpr int NB_   = 4;
constexpr int NG_   = 2;
constexpr float NEG_ = 0.01f;

constexpr int TI = 128;            // i-tile (stages 2/3)
constexpr int NTILES = N_ / TI;    // 16
constexpr int KC = 64;             // k-chunk
constexpr int NCH = N_ / KC;       // 32 (stage1)
constexpr int NT64 = N_ / 64;      // 32 (dots tiles / stage1 i-tiles)

constexpr int SW_BYTES = 144;      // 64 x 16-bit + 8 pad -> conflict-free frags

// stage-1 smem (fp16 single, 64-row i-tile, double-buffered, 2 CTAs/SM)
constexpr int TI1 = 64;
constexpr int OFF_C0   = 0;
constexpr int OFF_WN   = 1024;
constexpr int OFF_WP   = 2048;
constexpr int OFF_NORM = 6144;
constexpr int OFF_PROJ = 6656;     // ends 8704
constexpr int DBUF1    = TI1 * SW_BYTES;   // 9216
constexpr int WBUF     = 256 * SW_BYTES;   // 36864
constexpr int OFF_D    = 9728;             // 2 bufs
constexpr int OFF_W    = OFF_D + 2 * DBUF1;  // 28160, 2 bufs
constexpr int SMEM_SZ1 = OFF_W + 2 * WBUF;   // 101888 (99.5KB -> 2 CTAs/SM)

// stage-2 smem layout (bf16 3-split, unchanged)
constexpr int OFF2_C0 = 0;
constexpr int OFF2_A  = 1024;
constexpr int OFF2_AL = OFF2_A  + 128 * SW_BYTES;
constexpr int OFF2_WH = OFF2_AL + 128 * SW_BYTES;
constexpr int OFF2_WL = OFF2_WH + 256 * SW_BYTES;
constexpr int SMEM_SZ2 = OFF2_WL + 256 * SW_BYTES;  // 111616

// stage-3 smem layout (unchanged)
constexpr int OFF3_X   = 0;
constexpr int OFF3_RED = 2048;
constexpr int OFF3_A   = 5120;
constexpr int OFF3_AL  = OFF3_A  + 128 * SW_BYTES;
constexpr int OFF3_WH  = OFF3_AL + 128 * SW_BYTES;
constexpr int OFF3_WL  = OFF3_WH + 128 * SW_BYTES;
constexpr int SMEM_SZ3 = OFF3_WL + 128 * SW_BYTES;   // 78848
}

// Scratch (allocation-free device globals)
__device__ __half g_D  [(size_t)B_ * N_ * N_];         // sqrt(x x^T) fp16, 134MB
__device__ __nv_bfloat16 g_h1h[(size_t)B_ * N_ * H_];
__device__ __nv_bfloat16 g_h1l[(size_t)B_ * N_ * H_];
__device__ __nv_bfloat16 g_h2h[(size_t)B_ * N_ * H_];
__device__ __nv_bfloat16 g_h2l[(size_t)B_ * N_ * H_];
__device__ float g_part[(size_t)B_ * NTILES * KOUT_ * 3];
__device__ __half g_W1f [(size_t)H_ * N_];             // W1d^T fp16 [h][j]
__device__ __nv_bfloat16 g_W2h[(size_t)H_ * H_];
__device__ __nv_bfloat16 g_W2l[(size_t)H_ * H_];
__device__ __nv_bfloat16 g_W3h[(size_t)KOUT_ * H_];
__device__ __nv_bfloat16 g_W3l[(size_t)KOUT_ * H_];

// ===========================================================================
// Helpers
// ===========================================================================
__device__ __forceinline__ float fsqrt_fast(float v) {
    float r;
    asm("sqrt.approx.f32 %0, %1;" : "=f"(r) : "f"(v));
    return r;
}
__device__ __forceinline__ float lrelu(float v) { return v > 0.f ? v : NEG_ * v; }

union Pack8  { __nv_bfloat16 h[8]; uint4 v; };
union Pack8h { __half h[8]; uint4 v; };

__device__ __forceinline__ void mma16816(float* d, const uint32_t* a, const uint32_t* b) {
    asm volatile(
        "mma.sync.aligned.m16n8k16.row.col.f32.bf16.bf16.f32 "
        "{%0,%1,%2,%3}, {%4,%5,%6,%7}, {%8,%9}, {%0,%1,%2,%3};"
        : "+f"(d[0]), "+f"(d[1]), "+f"(d[2]), "+f"(d[3])
        : "r"(a[0]), "r"(a[1]), "r"(a[2]), "r"(a[3]), "r"(b[0]), "r"(b[1]));
}
__device__ __forceinline__ void mma16816h(float* d, const uint32_t* a, const uint32_t* b) {
    asm volatile(
        "mma.sync.aligned.m16n8k16.row.col.f32.f16.f16.f32 "
        "{%0,%1,%2,%3}, {%4,%5,%6,%7}, {%8,%9}, {%0,%1,%2,%3};"
        : "+f"(d[0]), "+f"(d[1]), "+f"(d[2]), "+f"(d[3])
        : "r"(a[0]), "r"(a[1]), "r"(a[2]), "r"(a[3]), "r"(b[0]), "r"(b[1]));
}
__device__ __forceinline__ uint32_t lds32(const char* smem, int off) {
    return *(const uint32_t*)(smem + off);
}
__device__ __forceinline__ uint32_t smem_u32(const void* p) {
    uint32_t a;
    asm("{ .reg .u64 t; cvta.to.shared.u64 t, %1; cvt.u32.u64 %0, t; }" : "=r"(a) : "l"(p));
    return a;
}
__device__ __forceinline__ void cp_async16(uint32_t dst, const void* src) {
    asm volatile("cp.async.cg.shared.global [%0], [%1], 16;"
                 :: "r"(dst), "l"(__cvta_generic_to_global(src)) : "memory");
}
__device__ __forceinline__ void cp_async_commit() {
    asm volatile("cp.async.commit_group;" ::: "memory");
}
__device__ __forceinline__ void cp_async_wait_all() {
    asm volatile("cp.async.wait_all;" ::: "memory");
}
__device__ __forceinline__ void split_store2(__nv_bfloat16* ph, __nv_bfloat16* pl,
                                             size_t idx, float z0, float z1) {
    __nv_bfloat16 h0 = __float2bfloat16_rn(z0);
    __nv_bfloat16 h1 = __float2bfloat16_rn(z1);
    __nv_bfloat162 vh; vh.x = h0; vh.y = h1;
    __nv_bfloat162 vl;
    vl.x = __float2bfloat16_rn(z0 - __bfloat162float(h0));
    vl.y = __float2bfloat16_rn(z1 - __bfloat162float(h1));
    *reinterpret_cast<__nv_bfloat162*>(ph + idx) = vh;
    *reinterpret_cast<__nv_bfloat162*>(pl + idx) = vl;
}

// ===========================================================================
// Prep kernels
// ===========================================================================
__global__ void k_prep_t(const float* __restrict__ src, __nv_bfloat16* dh,
                         __nv_bfloat16* dl, int R, int C) {
    __shared__ float tile[32][33];
    const int rb = blockIdx.x * 32, cb = blockIdx.y * 32;
    const int tx = threadIdx.x, ty = threadIdx.y;
    for (int r = ty; r < 32; r += 8)
        tile[r][tx] = src[(size_t)(rb + r) * C + cb + tx];
    __syncthreads();
    for (int r = ty; r < 32; r += 8) {
        const int cc = cb + r, rr = rb + tx;
        float v = tile[tx][r];
        __nv_bfloat16 hi = __float2bfloat16_rn(v);
        dh[(size_t)cc * R + rr] = hi;
        dl[(size_t)cc * R + rr] = __float2bfloat16_rn(v - __bfloat162float(hi));
    }
}
__global__ void k_prep_f16(const float* __restrict__ src, __half* dst, int R, int C) {
    __shared__ float tile[32][33];
    const int rb = blockIdx.x * 32, cb = blockIdx.y * 32;
    const int tx = threadIdx.x, ty = threadIdx.y;
    for (int r = ty; r < 32; r += 8)
        tile[r][tx] = src[(size_t)(rb + r) * C + cb + tx];
    __syncthreads();
    for (int r = ty; r < 32; r += 8)
        dst[(size_t)(cb + r) * R + rb + tx] = __float2half_rn(tile[tx][r]);
}

// ===========================================================================
// Stage 0: D = sqrt(x x^T) fp16, symmetric — upper-tri 64x64 tiles, write
// tile + transpose. Grid (NT64, NT64, B), 256 thr; ti>tj CTAs exit.
// ===========================================================================
__global__ __launch_bounds__(256)
void k_dots(const float* __restrict__ x) {
    const int ti = blockIdx.x, tj = blockIdx.y, b = blockIdx.z;
    if (ti > tj) return;
    const int I0 = ti * 64, J0 = tj * 64;
    const float* xb = x + (size_t)b * N_ * 3;

    __shared__ float sxi[192], sxj[192];
    __shared__ __half tile[64][72];

    const int t = threadIdx.x;
    if (t < 192) {
        sxi[t] = xb[(size_t)I0 * 3 + t];
        sxj[t] = xb[(size_t)J0 * 3 + t];
    }
    __syncthreads();

    const int r  = t >> 2;
    const int c0 = (t & 3) * 16;
    const float a0 = sxi[r * 3 + 0], a1 = sxi[r * 3 + 1], a2 = sxi[r * 3 + 2];

    Pack8h p0, p1;
#pragma unroll
    for (int e = 0; e < 8; e++) {
        const int j = c0 + e;
        p0.h[e] = __float2half_rn(fsqrt_fast(
            a0 * sxj[j * 3 + 0] + a1 * sxj[j * 3 + 1] + a2 * sxj[j * 3 + 2]));
    }
#pragma unroll
    for (int e = 0; e < 8; e++) {
        const int j = c0 + 8 + e;
        p1.h[e] = __float2half_rn(fsqrt_fast(
            a0 * sxj[j * 3 + 0] + a1 * sxj[j * 3 + 1] + a2 * sxj[j * 3 + 2]));
    }

    __half* drow = g_D + ((size_t)b * N_ + I0 + r) * N_ + J0 + c0;
    *(uint4*)(drow)     = p0.v;
    *(uint4*)(drow + 8) = p1.v;

    if (ti == tj) return;

    *(uint4*)(&tile[r][c0])     = p0.v;
    *(uint4*)(&tile[r][c0 + 8]) = p1.v;
    __syncthreads();

    Pack8h q0, q1;
#pragma unroll
    for (int e = 0; e < 8; e++)  q0.h[e] = tile[c0 + e][r];
#pragma unroll
    for (int e = 0; e < 8; e++)  q1.h[e] = tile[c0 + 8 + e][r];
    __half* drow2 = g_D + ((size_t)b * N_ + J0 + r) * N_ + I0 + c0;
    *(uint4*)(drow2)     = q0.v;
    *(uint4*)(drow2 + 8) = q1.v;
}

// ===========================================================================
// Stage 1 (pure fp16 GEMM, 64-row i-tile, 2 CTAs/SM)
// h1 = leaky(base + D @ W1d) -> bf16 hi/lo.  Grid (NT64, B).
// Warp tile 32 rows x 64 cols.
// ===========================================================================
__global__ __launch_bounds__(256, 2)
void k_stage1(const float* __restrict__ x, const float* __restrict__ u,
              const float* __restrict__ basis, const float* __restrict__ W1,
              const float* __restrict__ b1) {
    extern __shared__ char smem[];
    const uint32_t sbase = smem_u32(smem);
    const int t = threadIdx.x, w = t >> 5, lane = t & 31;
    const int i0 = blockIdx.x * TI1, b = blockIdx.y;
    const float* xb = x + (size_t)b * N_ * 3;

    float* c0    = (float*)(smem + OFF_C0);
    float* wn    = (float*)(smem + OFF_WN);
    float* wpp   = (float*)(smem + OFF_WP);
    float* snorm = (float*)(smem + OFF_NORM);
    float* sproj = (float*)(smem + OFF_PROJ);

    if (t < H_) {
        const float u0 = u[b * NG_ + 0], u1 = u[b * NG_ + 1];
        c0[t] = b1[t] + u0 * W1[t] + u1 * W1[H_ + t];
        wn[t] = W1[2 * H_ + t];
#pragma unroll
        for (int k = 0; k < NB_; k++) wpp[k * H_ + t] = W1[(3 + k) * H_ + t];
    }
    if (t < TI1) {
        const float y0 = xb[(i0 + t) * 3 + 0];
        const float y1 = xb[(i0 + t) * 3 + 1];
        const float y2 = xb[(i0 + t) * 3 + 2];
        snorm[t] = fsqrt_fast(y0 * y0 + y1 * y1 + y2 * y2);
#pragma unroll
        for (int k = 0; k < NB_; k++) {
            const float* bk = basis + ((size_t)b * NB_ + k) * 3;
            sproj[t * NB_ + k] = y0 * bk[0] + y1 * bk[1] + y2 * bk[2];
        }
    }

    const int wrow = (w & 1) * 32;
    const int wcol = (w >> 1) * 64;
    const int g = lane >> 2;
    const int c = lane & 3;

    float acc[2][8][4];     // 64 regs
#pragma unroll
    for (int mi = 0; mi < 2; mi++)
#pragma unroll
        for (int ni = 0; ni < 8; ni++)
#pragma unroll
            for (int e = 0; e < 4; e++) acc[mi][ni][e] = 0.f;

    const __half* Dbase = g_D + ((size_t)b * N_ + i0) * N_;

    auto issue_chunk = [&](int ch, int buf) {
        const int wbase = OFF_W + buf * WBUF;
#pragma unroll
        for (int m = 0; m < 8; m++) {
            const int q = t + m * 256;
            const int row = q >> 3, seg = q & 7;
            cp_async16(sbase + wbase + row * SW_BYTES + seg * 16,
                       g_W1f + (size_t)row * N_ + ch * KC + seg * 8);
        }
        const int dbase = OFF_D + buf * DBUF1;
#pragma unroll
        for (int m = 0; m < 2; m++) {
            const int q = t + m * 256;
            const int row = q >> 3, seg = q & 7;
            cp_async16(sbase + dbase + row * SW_BYTES + seg * 16,
                       Dbase + (size_t)row * N_ + ch * KC + seg * 8);
        }
        cp_async_commit();
    };

    issue_chunk(0, 0);
    cp_async_wait_all();
    __syncthreads();

    for (int ch = 0; ch < NCH; ch++) {
        const int buf = ch & 1;
        const bool more = (ch < NCH - 1);
        if (more) issue_chunk(ch + 1, buf ^ 1);

        const int offD = OFF_D + buf * DBUF1;
        const int offW = OFF_W + buf * WBUF;

#pragma unroll
        for (int k16 = 0; k16 < 4; k16++) {
            const int wb = (k16 * 8 + c) * 4;
            uint32_t bh[8][2];
#pragma unroll
            for (int ni = 0; ni < 8; ni++) {
                const int rb = (wcol + ni * 8 + g) * SW_BYTES;
                bh[ni][0] = lds32(smem, offW + rb + wb);
                bh[ni][1] = lds32(smem, offW + rb + wb + 16);
            }
#pragma unroll
            for (int mi = 0; mi < 2; mi++) {
                const int r0 = (wrow + mi * 16 + g) * SW_BYTES;
                const int r8 = r0 + 8 * SW_BYTES;
                uint32_t ah[4];
                ah[0] = lds32(smem, offD + r0 + wb);
                ah[1] = lds32(smem, offD + r8 + wb);
                ah[2] = lds32(smem, offD + r0 + wb + 16);
                ah[3] = lds32(smem, offD + r8 + wb + 16);
#pragma unroll
                for (int ni = 0; ni < 8; ni++) mma16816h(acc[mi][ni], ah, bh[ni]);
            }
        }

        cp_async_wait_all();
        __syncthreads();
    }

    // epilogue: exact fp32 base terms, LeakyReLU, store bf16 hi/lo
#pragma unroll
    for (int mi = 0; mi < 2; mi++) {
#pragma unroll
        for (int rr = 0; rr < 2; rr++) {
            const int row = wrow + mi * 16 + g + rr * 8;
            const float nrm = snorm[row];
            const float p0 = sproj[row * NB_ + 0], p1 = sproj[row * NB_ + 1];
            const float p2 = sproj[row * NB_ + 2], p3 = sproj[row * NB_ + 3];
            const size_t rbase = ((size_t)b * N_ + i0 + row) * H_;
#pragma unroll
            for (int ni = 0; ni < 8; ni++) {
                const int col = wcol + ni * 8 + c * 2;
                float z[2];
#pragma unroll
                for (int e = 0; e < 2; e++) {
                    const int h = col + e;
                    float zz = acc[mi][ni][rr * 2 + e] + c0[h] + nrm * wn[h]
                             + p0 * wpp[h] + p1 * wpp[H_ + h]
                             + p2 * wpp[2 * H_ + h] + p3 * wpp[3 * H_ + h];
                    z[e] = lrelu(zz);
                }
                split_store2(g_h1h, g_h1l, rbase + col, z[0], z[1]);
            }
        }
    }
}

// ===========================================================================
// Stage 2 (bf16 3-split HMMA): h2 = leaky(h1 @ W2 + b2) -> bf16 hi/lo
// ===========================================================================
__global__ __launch_bounds__(256, 1)
void k_stage2(const float* __restrict__ b2) {
    extern __shared__ char smem[];
    const int t = threadIdx.x, w = t >> 5, lane = t & 31;
    const size_t row0 = (size_t)blockIdx.x * TI;

    float* c0 = (float*)(smem + OFF2_C0);
    if (t < H_) c0[t] = b2[t];

    const int wrow = (w & 1) * 64;
    const int wcol = (w >> 1) * 64;
    const int g = lane >> 2;
    const int c = lane & 3;

    float acc[4][8][4];
#pragma unroll
    for (int mi = 0; mi < 4; mi++)
#pragma unroll
        for (int ni = 0; ni < 8; ni++)
#pragma unroll
            for (int e = 0; e < 4; e++) acc[mi][ni][e] = 0.f;

    for (int ch = 0; ch < 4; ch++) {
        const int k0 = ch * KC;
        __syncthreads();
#pragma unroll
        for (int m = 0; m < 4; m++) {
            const int q = t + m * 256;
            const int row = q >> 3, seg = q & 7;
            const int dst = row * SW_BYTES + seg * 16;
            const size_t src = (row0 + row) * H_ + k0 + seg * 8;
            *(uint4*)(smem + OFF2_A  + dst) = *(const uint4*)(g_h1h + src);
            *(uint4*)(smem + OFF2_AL + dst) = *(const uint4*)(g_h1l + src);
        }
#pragma unroll
        for (int m = 0; m < 8; m++) {
            const int q = t + m * 256;
            const int row = q >> 3, seg = q & 7;
            const int dst = row * SW_BYTES + seg * 16;
            const size_t src = (size_t)row * H_ + k0 + seg * 8;
            *(uint4*)(smem + OFF2_WH + dst) = *(const uint4*)(g_W2h + src);
            *(uint4*)(smem + OFF2_WL + dst) = *(const uint4*)(g_W2l + src);
        }
        __syncthreads();

#pragma unroll
        for (int k16 = 0; k16 < 4; k16++) {
            const int wb = (k16 * 8 + c) * 4;
            uint32_t bh[8][2], bl[8][2];
#pragma unroll
            for (int ni = 0; ni < 8; ni++) {
                const int rb = (wcol + ni * 8 + g) * SW_BYTES;
                bh[ni][0] = lds32(smem, OFF2_WH + rb + wb);
                bh[ni][1] = lds32(smem, OFF2_WH + rb + wb + 16);
                bl[ni][0] = lds32(smem, OFF2_WL + rb + wb);
                bl[ni][1] = lds32(smem, OFF2_WL + rb + wb + 16);
            }
#pragma unroll
            for (int mi = 0; mi < 4; mi++) {
                const int r0 = (wrow + mi * 16 + g) * SW_BYTES;
                const int r8 = r0 + 8 * SW_BYTES;
                uint32_t ah[4], al[4];
                ah[0] = lds32(smem, OFF2_A  + r0 + wb);
                ah[1] = lds32(smem, OFF2_A  + r8 + wb);
                ah[2] = lds32(smem, OFF2_A  + r0 + wb + 16);
                ah[3] = lds32(smem, OFF2_A  + r8 + wb + 16);
                al[0] = lds32(smem, OFF2_AL + r0 + wb);
                al[1] = lds32(smem, OFF2_AL + r8 + wb);
                al[2] = lds32(smem, OFF2_AL + r0 + wb + 16);
                al[3] = lds32(smem, OFF2_AL + r8 + wb + 16);
#pragma unroll
                for (int ni = 0; ni < 8; ni++) mma16816(acc[mi][ni], ah, bh[ni]);
#pragma unroll
                for (int ni = 0; ni < 8; ni++) mma16816(acc[mi][ni], al, bh[ni]);
#pragma unroll
                for (int ni = 0; ni < 8; ni++) mma16816(acc[mi][ni], ah, bl[ni]);
            }
        }
    }

#pragma unroll
    for (int mi = 0; mi < 4; mi++) {
#pragma unroll
        for (int rr = 0; rr < 2; rr++) {
            const int row = wrow + mi * 16 + g + rr * 8;
            const size_t rbase = (row0 + row) * H_;
#pragma unroll
            for (int ni = 0; ni < 8; ni++) {
                const int col = wcol + ni * 8 + c * 2;
                float z0 = lrelu(acc[mi][ni][rr * 2 + 0] + c0[col]);
                float z1 = lrelu(acc[mi][ni][rr * 2 + 1] + c0[col + 1]);
                split_store2(g_h2h, g_h2l, rbase + col, z0, z1);
            }
        }
    }
}

// ===========================================================================
// Stage 3 (bf16 3-split HMMA): fk = h2 @ W3 + b3 fused with contraction
// ===========================================================================
__global__ __launch_bounds__(256, 1)
void k_stage3(const float* __restrict__ x, const float* __restrict__ b3) {
    extern __shared__ char smem[];
    const int t = threadIdx.x, w = t >> 5, lane = t & 31;
    const int i0 = blockIdx.x * TI, b = blockIdx.y;

    float* sx   = (float*)(smem + OFF3_X);
    float* sred = (float*)(smem + OFF3_RED);

    if (t < TI) {
        const float* xp = x + ((size_t)b * N_ + i0 + t) * 3;
        sx[t * 4 + 0] = xp[0]; sx[t * 4 + 1] = xp[1]; sx[t * 4 + 2] = xp[2];
    }

    const int wrow = (w & 1) * 64;
    const int wcol = (w >> 1) * 32;
    const int g = lane >> 2;
    const int c = lane & 3;

    float acc[4][4][4];
#pragma unroll
    for (int mi = 0; mi < 4; mi++)
#pragma unroll
        for (int ni = 0; ni < 4; ni++)
#pragma unroll
            for (int e = 0; e < 4; e++) acc[mi][ni][e] = 0.f;

    const size_t row0 = (size_t)b * N_ + i0;

    for (int ch = 0; ch < 4; ch++) {
        const int k0 = ch * KC;
        __syncthreads();
#pragma unroll
        for (int m = 0; m < 4; m++) {
            const int q = t + m * 256;
            const int row = q >> 3, seg = q & 7;
            const int dst = row * SW_BYTES + seg * 16;
            const size_t src = (row0 + row) * H_ + k0 + seg * 8;
            *(uint4*)(smem + OFF3_A  + dst) = *(const uint4*)(g_h2h + src);
            *(uint4*)(smem + OFF3_AL + dst) = *(const uint4*)(g_h2l + src);
        }
#pragma unroll
        for (int m = 0; m < 4; m++) {
            const int q = t + m * 256;
            const int row = q >> 3, seg = q & 7;
            const int dst = row * SW_BYTES + seg * 16;
            const size_t src = (size_t)row * H_ + k0 + seg * 8;
            *(uint4*)(smem + OFF3_WH + dst) = *(const uint4*)(g_W3h + src);
            *(uint4*)(smem + OFF3_WL + dst) = *(const uint4*)(g_W3l + src);
        }
        __syncthreads();

#pragma unroll
        for (int k16 = 0; k16 < 4; k16++) {
            const int wb = (k16 * 8 + c) * 4;
            uint32_t bh[4][2], bl[4][2];
#pragma unroll
            for (int ni = 0; ni < 4; ni++) {
                const int rb = (wcol + ni * 8 + g) * SW_BYTES;
                bh[ni][0] = lds32(smem, OFF3_WH + rb + wb);
                bh[ni][1] = lds32(smem, OFF3_WH + rb + wb + 16);
                bl[ni][0] = lds32(smem, OFF3_WL + rb + wb);
                bl[ni][1] = lds32(smem, OFF3_WL + rb + wb + 16);
            }
#pragma unroll
            for (int mi = 0; mi < 4; mi++) {
                const int r0 = (wrow + mi * 16 + g) * SW_BYTES;
                const int r8 = r0 + 8 * SW_BYTES;
                uint32_t ah[4], al[4];
                ah[0] = lds32(smem, OFF3_A  + r0 + wb);
                ah[1] = lds32(smem, OFF3_A  + r8 + wb);
                ah[2] = lds32(smem, OFF3_A  + r0 + wb + 16);
                ah[3] = lds32(smem, OFF3_A  + r8 + wb + 16);
                al[0] = lds32(smem, OFF3_AL + r0 + wb);
                al[1] = lds32(smem, OFF3_AL + r8 + wb);
                al[2] = lds32(smem, OFF3_AL + r0 + wb + 16);
                al[3] = lds32(smem, OFF3_AL + r8 + wb + 16);
#pragma unroll
                for (int ni = 0; ni < 4; ni++) mma16816(acc[mi][ni], ah, bh[ni]);
#pragma unroll
                for (int ni = 0; ni < 4; ni++) mma16816(acc[mi][ni], al, bh[ni]);
#pragma unroll
                for (int ni = 0; ni < 4; ni++) mma16816(acc[mi][ni], ah, bl[ni]);
            }
        }
    }

    float b3c[8];
#pragma unroll
    for (int ni = 0; ni < 4; ni++)
#pragma unroll
        for (int e = 0; e < 2; e++)
            b3c[ni * 2 + e] = b3[wcol + ni * 8 + c * 2 + e];

    float po[8][3];
#pragma unroll
    for (int k = 0; k < 8; k++) { po[k][0] = 0.f; po[k][1] = 0.f; po[k][2] = 0.f; }

#pragma unroll
    for (int mi = 0; mi < 4; mi++) {
#pragma unroll
        for (int rr = 0; rr < 2; rr++) {
            const int row = wrow + mi * 16 + g + rr * 8;
            const float x0 = sx[row * 4 + 0];
            const float x1 = sx[row * 4 + 1];
            const float x2 = sx[row * 4 + 2];
#pragma unroll
            for (int ni = 0; ni < 4; ni++) {
#pragma unroll
                for (int e = 0; e < 2; e++) {
                    const float f = acc[mi][ni][rr * 2 + e] + b3c[ni * 2 + e];
                    po[ni * 2 + e][0] = fmaf(f, x0, po[ni * 2 + e][0]);
                    po[ni * 2 + e][1] = fmaf(f, x1, po[ni * 2 + e][1]);
                    po[ni * 2 + e][2] = fmaf(f, x2, po[ni * 2 + e][2]);
                }
            }
        }
    }
#pragma unroll
    for (int k = 0; k < 8; k++)
#pragma unroll
        for (int d = 0; d < 3; d++) {
            po[k][d] += __shfl_down_sync(0xffffffffu, po[k][d], 16);
            po[k][d] += __shfl_down_sync(0xffffffffu, po[k][d], 8);
            po[k][d] += __shfl_down_sync(0xffffffffu, po[k][d], 4);
        }
    if (lane < 4) {
#pragma unroll
        for (int k = 0; k < 8; k++)
#pragma unroll
            for (int d = 0; d < 3; d++)
                sred[((w * 4 + lane) * 8 + k) * 3 + d] = po[k][d];
    }
    __syncthreads();

    if (t < KOUT_) {
        const int o = t;
        const int w0 = (o >> 5) * 2;
        const int cc = (o & 7) >> 1;
        const int kk = ((o >> 3) & 3) * 2 + (o & 1);
        float s[3];
#pragma unroll
        for (int d = 0; d < 3; d++)
            s[d] = sred[(((w0)     * 4 + cc) * 8 + kk) * 3 + d]
                 + sred[(((w0 + 1) * 4 + cc) * 8 + kk) * 3 + d];
        const size_t base = (((size_t)b * NTILES + blockIdx.x) * KOUT_ + o) * 3;
        g_part[base + 0] = s[0]; g_part[base + 1] = s[1]; g_part[base + 2] = s[2];
    }
}

// ===========================================================================
// Stage 4: reduce tiles
// ===========================================================================
__global__ void k_reduce(float* __restrict__ out) {
    int t = blockIdx.x * blockDim.x + threadIdx.x;
    if (t >= B_ * KOUT_ * 3) return;
    int b = t / (KOUT_ * 3), rem = t % (KOUT_ * 3);
    float s = 0.f;
#pragma unroll
    for (int tile = 0; tile < NTILES; tile++)
        s += g_part[((size_t)b * NTILES + tile) * KOUT_ * 3 + rem];
    out[t] = s * (1.0f / N_);
}

// ===========================================================================
extern "C" void kernel_launch(void* const* d_in, const int* in_sizes, int n_in,
                              void* d_out, int out_size) {
    const float* x     = (const float*)d_in[0];
    const float* u     = (const float*)d_in[1];
    const float* basis = (const float*)d_in[2];
    const float* W1    = (const float*)d_in[3];
    const float* b1    = (const float*)d_in[4];
    const float* W2    = (const float*)d_in[5];
    const float* b2    = (const float*)d_in[6];
    const float* W3    = (const float*)d_in[7];
    const float* b3    = (const float*)d_in[8];
    float* out = (float*)d_out;

    cudaFuncSetAttribute(k_stage1, cudaFuncAttributeMaxDynamicSharedMemorySize, SMEM_SZ1);
    cudaFuncSetAttribute(k_stage2, cudaFuncAttributeMaxDynamicSharedMemorySize, SMEM_SZ2);
    cudaFuncSetAttribute(k_stage3, cudaFuncAttributeMaxDynamicSharedMemorySize, SMEM_SZ3);

    __half* dW1f;
    __nv_bfloat16 *dW2h, *dW2l, *dW3h, *dW3l;
    cudaGetSymbolAddress((void**)&dW1f, g_W1f);
    cudaGetSymbolAddress((void**)&dW2h, g_W2h);
    cudaGetSymbolAddress((void**)&dW2l, g_W2l);
    cudaGetSymbolAddress((void**)&dW3h, g_W3h);
    cudaGetSymbolAddress((void**)&dW3l, g_W3l);

    k_prep_f16<<<dim3(N_ / 32, H_ / 32), dim3(32, 8)>>>(W1 + 7 * H_, dW1f, N_, H_);
    k_prep_t<<<dim3(H_ / 32, H_ / 32), dim3(32, 8)>>>(W2, dW2h, dW2l, H_, H_);
    k_prep_t<<<dim3(H_ / 32, KOUT_ / 32), dim3(32, 8)>>>(W3, dW3h, dW3l, H_, KOUT_);

    k_dots<<<dim3(NT64, NT64, B_), 256>>>(x);
    k_stage1<<<dim3(NT64, B_), 256, SMEM_SZ1>>>(x, u, basis, W1, b1);
    k_stage2<<<(B_ * N_) / TI, 256, SMEM_SZ2>>>(b2);
    k_stage3<<<dim3(NTILES, B_), 256, SMEM_SZ3>>>(x, b3);
    k_reduce<<<(B_ * KOUT_ * 3 + 255) / 256, 256>>>(out);
}

// round 17
// speedup vs baseline: 1.2499x; 1.2499x over previous
#include <cuda_runtime.h>
#include <cuda_bf16.h>
#include <cuda_fp16.h>
#include <stdint.h>

// ===========================================================================
// Problem constants
// ===========================================================================
namespace {
constexpr int B_    = 16;
constexpr int N_    = 2048;
constexpr int H_    = 256;
constexpr int KOUT_ = 128;
constexpr int NB_   = 4;
constexpr int NG_   = 2;
constexpr float NEG_ = 0.01f;

constexpr int TI = 128;            // i-tile
constexpr int NTILES = N_ / TI;    // 16
constexpr int KC = 64;             // k-chunk
constexpr int NCH = N_ / KC;       // 32 (stage1)
constexpr int NT64 = N_ / 64;      // 32 (dots tiles)

constexpr int SW_BYTES = 144;      // 64 x 16-bit + 8 pad -> conflict-free frags

// stage-1 smem (fp16 single, 128-row i-tile, double-buffered) — R15 layout
constexpr int OFF_C0   = 0;
constexpr int OFF_WN   = 1024;
constexpr int OFF_WP   = 2048;
constexpr int OFF_NORM = 6144;
constexpr int OFF_PROJ = 6656;     // ends 8704
constexpr int DBUF     = 128 * SW_BYTES;   // 18432
constexpr int WBUF     = 256 * SW_BYTES;   // 36864
constexpr int OFF_D    = 9728;             // 2 bufs
constexpr int OFF_W    = OFF_D + 2 * DBUF; // 46592, 2 bufs
constexpr int SMEM_SZ1 = OFF_W + 2 * WBUF; // 120320 (117.5KB)

// stage-2 smem (fp16 single)
constexpr int OFF2_C0 = 0;
constexpr int OFF2_A  = 1024;
constexpr int OFF2_W  = OFF2_A + 128 * SW_BYTES;
constexpr int SMEM_SZ2 = OFF2_W + 256 * SW_BYTES;   // 56320

// stage-3 smem (fp16 single)
constexpr int OFF3_X   = 0;
constexpr int OFF3_RED = 2048;
constexpr int OFF3_A   = 5120;
constexpr int OFF3_W   = OFF3_A + 128 * SW_BYTES;
constexpr int SMEM_SZ3 = OFF3_W + 128 * SW_BYTES;   // 41984
}

// Scratch (allocation-free device globals)
__device__ __half g_D  [(size_t)B_ * N_ * N_];         // sqrt(x x^T) fp16
__device__ __half g_h1f[(size_t)B_ * N_ * H_];
__device__ __half g_h2f[(size_t)B_ * N_ * H_];
__device__ float g_part[(size_t)B_ * NTILES * KOUT_ * 3];
__device__ __half g_W1f[(size_t)H_ * N_];              // W1d^T fp16 [h][j]
__device__ __half g_W2f[(size_t)H_ * H_];              // W2^T fp16 [hout][hin]
__device__ __half g_W3f[(size_t)KOUT_ * H_];           // W3^T fp16 [o][h]

// ===========================================================================
// Helpers
// ===========================================================================
__device__ __forceinline__ float fsqrt_fast(float v) {
    float r;
    asm("sqrt.approx.f32 %0, %1;" : "=f"(r) : "f"(v));
    return r;
}
__device__ __forceinline__ float lrelu(float v) { return v > 0.f ? v : NEG_ * v; }

union Pack8h { __half h[8]; uint4 v; };

__device__ __forceinline__ void mma16816h(float* d, const uint32_t* a, const uint32_t* b) {
    asm volatile(
        "mma.sync.aligned.m16n8k16.row.col.f32.f16.f16.f32 "
        "{%0,%1,%2,%3}, {%4,%5,%6,%7}, {%8,%9}, {%0,%1,%2,%3};"
        : "+f"(d[0]), "+f"(d[1]), "+f"(d[2]), "+f"(d[3])
        : "r"(a[0]), "r"(a[1]), "r"(a[2]), "r"(a[3]), "r"(b[0]), "r"(b[1]));
}
__device__ __forceinline__ uint32_t lds32(const char* smem, int off) {
    return *(const uint32_t*)(smem + off);
}
__device__ __forceinline__ uint32_t smem_u32(const void* p) {
    uint32_t a;
    asm("{ .reg .u64 t; cvta.to.shared.u64 t, %1; cvt.u32.u64 %0, t; }" : "=r"(a) : "l"(p));
    return a;
}
__device__ __forceinline__ void cp_async16(uint32_t dst, const void* src) {
    asm volatile("cp.async.cg.shared.global [%0], [%1], 16;"
                 :: "r"(dst), "l"(__cvta_generic_to_global(src)) : "memory");
}
__device__ __forceinline__ void cp_async_commit() {
    asm volatile("cp.async.commit_group;" ::: "memory");
}
__device__ __forceinline__ void cp_async_wait_all() {
    asm volatile("cp.async.wait_all;" ::: "memory");
}
__device__ __forceinline__ void store2h(__half* p, size_t idx, float z0, float z1) {
    __half2 v;
    v.x = __float2half_rn(z0);
    v.y = __float2half_rn(z1);
    *reinterpret_cast<__half2*>(p + idx) = v;
}

// ===========================================================================
// Prep: transpose + fp16
// ===========================================================================
__global__ void k_prep_f16(const float* __restrict__ src, __half* dst, int R, int C) {
    __shared__ float tile[32][33];
    const int rb = blockIdx.x * 32, cb = blockIdx.y * 32;
    const int tx = threadIdx.x, ty = threadIdx.y;
    for (int r = ty; r < 32; r += 8)
        tile[r][tx] = src[(size_t)(rb + r) * C + cb + tx];
    __syncthreads();
    for (int r = ty; r < 32; r += 8)
        dst[(size_t)(cb + r) * R + rb + tx] = __float2half_rn(tile[tx][r]);
}

// ===========================================================================
// Stage 0: D = sqrt(x x^T) fp16, symmetric — upper-tri 64x64 tiles.
// ===========================================================================
__global__ __launch_bounds__(256)
void k_dots(const float* __restrict__ x) {
    const int ti = blockIdx.x, tj = blockIdx.y, b = blockIdx.z;
    if (ti > tj) return;
    const int I0 = ti * 64, J0 = tj * 64;
    const float* xb = x + (size_t)b * N_ * 3;

    __shared__ float sxi[192], sxj[192];
    __shared__ __half tile[64][72];

    const int t = threadIdx.x;
    if (t < 192) {
        sxi[t] = xb[(size_t)I0 * 3 + t];
        sxj[t] = xb[(size_t)J0 * 3 + t];
    }
    __syncthreads();

    const int r  = t >> 2;
    const int c0 = (t & 3) * 16;
    const float a0 = sxi[r * 3 + 0], a1 = sxi[r * 3 + 1], a2 = sxi[r * 3 + 2];

    Pack8h p0, p1;
#pragma unroll
    for (int e = 0; e < 8; e++) {
        const int j = c0 + e;
        p0.h[e] = __float2half_rn(fsqrt_fast(
            a0 * sxj[j * 3 + 0] + a1 * sxj[j * 3 + 1] + a2 * sxj[j * 3 + 2]));
    }
#pragma unroll
    for (int e = 0; e < 8; e++) {
        const int j = c0 + 8 + e;
        p1.h[e] = __float2half_rn(fsqrt_fast(
            a0 * sxj[j * 3 + 0] + a1 * sxj[j * 3 + 1] + a2 * sxj[j * 3 + 2]));
    }

    __half* drow = g_D + ((size_t)b * N_ + I0 + r) * N_ + J0 + c0;
    *(uint4*)(drow)     = p0.v;
    *(uint4*)(drow + 8) = p1.v;

    if (ti == tj) return;

    *(uint4*)(&tile[r][c0])     = p0.v;
    *(uint4*)(&tile[r][c0 + 8]) = p1.v;
    __syncthreads();

    Pack8h q0, q1;
#pragma unroll
    for (int e = 0; e < 8; e++)  q0.h[e] = tile[c0 + e][r];
#pragma unroll
    for (int e = 0; e < 8; e++)  q1.h[e] = tile[c0 + 8 + e][r];
    __half* drow2 = g_D + ((size_t)b * N_ + J0 + r) * N_ + I0 + c0;
    *(uint4*)(drow2)     = q0.v;
    *(uint4*)(drow2 + 8) = q1.v;
}

// ===========================================================================
// Stage 1 (pure fp16 GEMM, R15 config): h1 = leaky(base + D @ W1d) -> fp16
// Grid (NTILES, B), 256 threads, warp tile 64x64.
// ===========================================================================
__global__ __launch_bounds__(256, 1)
void k_stage1(const float* __restrict__ x, const float* __restrict__ u,
              const float* __restrict__ basis, const float* __restrict__ W1,
              const float* __restrict__ b1) {
    extern __shared__ char smem[];
    const uint32_t sbase = smem_u32(smem);
    const int t = threadIdx.x, w = t >> 5, lane = t & 31;
    const int i0 = blockIdx.x * TI, b = blockIdx.y;
    const float* xb = x + (size_t)b * N_ * 3;

    float* c0    = (float*)(smem + OFF_C0);
    float* wn    = (float*)(smem + OFF_WN);
    float* wpp   = (float*)(smem + OFF_WP);
    float* snorm = (float*)(smem + OFF_NORM);
    float* sproj = (float*)(smem + OFF_PROJ);

    if (t < H_) {
        const float u0 = u[b * NG_ + 0], u1 = u[b * NG_ + 1];
        c0[t] = b1[t] + u0 * W1[t] + u1 * W1[H_ + t];
        wn[t] = W1[2 * H_ + t];
#pragma unroll
        for (int k = 0; k < NB_; k++) wpp[k * H_ + t] = W1[(3 + k) * H_ + t];
    }
    if (t < TI) {
        const float y0 = xb[(i0 + t) * 3 + 0];
        const float y1 = xb[(i0 + t) * 3 + 1];
        const float y2 = xb[(i0 + t) * 3 + 2];
        snorm[t] = fsqrt_fast(y0 * y0 + y1 * y1 + y2 * y2);
#pragma unroll
        for (int k = 0; k < NB_; k++) {
            const float* bk = basis + ((size_t)b * NB_ + k) * 3;
            sproj[t * NB_ + k] = y0 * bk[0] + y1 * bk[1] + y2 * bk[2];
        }
    }

    const int wrow = (w & 1) * 64;
    const int wcol = (w >> 1) * 64;
    const int g = lane >> 2;
    const int c = lane & 3;

    float acc[4][8][4];
#pragma unroll
    for (int mi = 0; mi < 4; mi++)
#pragma unroll
        for (int ni = 0; ni < 8; ni++)
#pragma unroll
            for (int e = 0; e < 4; e++) acc[mi][ni][e] = 0.f;

    const __half* Dbase = g_D + ((size_t)b * N_ + i0) * N_;

    auto issue_chunk = [&](int ch, int buf) {
        const int wbase = OFF_W + buf * WBUF;
#pragma unroll
        for (int m = 0; m < 8; m++) {
            const int q = t + m * 256;
            const int row = q >> 3, seg = q & 7;
            cp_async16(sbase + wbase + row * SW_BYTES + seg * 16,
                       g_W1f + (size_t)row * N_ + ch * KC + seg * 8);
        }
        const int dbase = OFF_D + buf * DBUF;
#pragma unroll
        for (int m = 0; m < 4; m++) {
            const int q = t + m * 256;
            const int row = q >> 3, seg = q & 7;
            cp_async16(sbase + dbase + row * SW_BYTES + seg * 16,
                       Dbase + (size_t)row * N_ + ch * KC + seg * 8);
        }
        cp_async_commit();
    };

    issue_chunk(0, 0);
    cp_async_wait_all();
    __syncthreads();

    for (int ch = 0; ch < NCH; ch++) {
        const int buf = ch & 1;
        const bool more = (ch < NCH - 1);
        if (more) issue_chunk(ch + 1, buf ^ 1);

        const int offD = OFF_D + buf * DBUF;
        const int offW = OFF_W + buf * WBUF;

#pragma unroll
        for (int k16 = 0; k16 < 4; k16++) {
            const int wb = (k16 * 8 + c) * 4;
            uint32_t bh[8][2];
#pragma unroll
            for (int ni = 0; ni < 8; ni++) {
                const int rb = (wcol + ni * 8 + g) * SW_BYTES;
                bh[ni][0] = lds32(smem, offW + rb + wb);
                bh[ni][1] = lds32(smem, offW + rb + wb + 16);
            }
#pragma unroll
            for (int mi = 0; mi < 4; mi++) {
                const int r0 = (wrow + mi * 16 + g) * SW_BYTES;
                const int r8 = r0 + 8 * SW_BYTES;
                uint32_t ah[4];
                ah[0] = lds32(smem, offD + r0 + wb);
                ah[1] = lds32(smem, offD + r8 + wb);
                ah[2] = lds32(smem, offD + r0 + wb + 16);
                ah[3] = lds32(smem, offD + r8 + wb + 16);
#pragma unroll
                for (int ni = 0; ni < 8; ni++) mma16816h(acc[mi][ni], ah, bh[ni]);
            }
        }

        cp_async_wait_all();
        __syncthreads();
    }

    // epilogue: exact fp32 base terms, LeakyReLU, store fp16
#pragma unroll
    for (int mi = 0; mi < 4; mi++) {
#pragma unroll
        for (int rr = 0; rr < 2; rr++) {
            const int row = wrow + mi * 16 + g + rr * 8;
            const float nrm = snorm[row];
            const float p0 = sproj[row * NB_ + 0], p1 = sproj[row * NB_ + 1];
            const float p2 = sproj[row * NB_ + 2], p3 = sproj[row * NB_ + 3];
            const size_t rbase = ((size_t)b * N_ + i0 + row) * H_;
#pragma unroll
            for (int ni = 0; ni < 8; ni++) {
                const int col = wcol + ni * 8 + c * 2;
                float z[2];
#pragma unroll
                for (int e = 0; e < 2; e++) {
                    const int h = col + e;
                    float zz = acc[mi][ni][rr * 2 + e] + c0[h] + nrm * wn[h]
                             + p0 * wpp[h] + p1 * wpp[H_ + h]
                             + p2 * wpp[2 * H_ + h] + p3 * wpp[3 * H_ + h];
                    z[e] = lrelu(zz);
                }
                store2h(g_h1f, rbase + col, z[0], z[1]);
            }
        }
    }
}

// ===========================================================================
// Stage 2 (fp16 single HMMA): h2 = leaky(h1 @ W2 + b2) -> fp16
// Grid (B*N/TI), 256 threads, warp tile 64x64.
// ===========================================================================
__global__ __launch_bounds__(256, 1)
void k_stage2(const float* __restrict__ b2) {
    extern __shared__ char smem[];
    const int t = threadIdx.x, w = t >> 5, lane = t & 31;
    const size_t row0 = (size_t)blockIdx.x * TI;

    float* c0 = (float*)(smem + OFF2_C0);
    if (t < H_) c0[t] = b2[t];

    const int wrow = (w & 1) * 64;
    const int wcol = (w >> 1) * 64;
    const int g = lane >> 2;
    const int c = lane & 3;

    float acc[4][8][4];
#pragma unroll
    for (int mi = 0; mi < 4; mi++)
#pragma unroll
        for (int ni = 0; ni < 8; ni++)
#pragma unroll
            for (int e = 0; e < 4; e++) acc[mi][ni][e] = 0.f;

    for (int ch = 0; ch < 4; ch++) {
        const int k0 = ch * KC;
        __syncthreads();
#pragma unroll
        for (int m = 0; m < 4; m++) {
            const int q = t + m * 256;
            const int row = q >> 3, seg = q & 7;
            *(uint4*)(smem + OFF2_A + row * SW_BYTES + seg * 16) =
                *(const uint4*)(g_h1f + (row0 + row) * H_ + k0 + seg * 8);
        }
#pragma unroll
        for (int m = 0; m < 8; m++) {
            const int q = t + m * 256;
            const int row = q >> 3, seg = q & 7;
            *(uint4*)(smem + OFF2_W + row * SW_BYTES + seg * 16) =
                *(const uint4*)(g_W2f + (size_t)row * H_ + k0 + seg * 8);
        }
        __syncthreads();

#pragma unroll
        for (int k16 = 0; k16 < 4; k16++) {
            const int wb = (k16 * 8 + c) * 4;
            uint32_t bh[8][2];
#pragma unroll
            for (int ni = 0; ni < 8; ni++) {
                const int rb = (wcol + ni * 8 + g) * SW_BYTES;
                bh[ni][0] = lds32(smem, OFF2_W + rb + wb);
                bh[ni][1] = lds32(smem, OFF2_W + rb + wb + 16);
            }
#pragma unroll
            for (int mi = 0; mi < 4; mi++) {
                const int r0 = (wrow + mi * 16 + g) * SW_BYTES;
                const int r8 = r0 + 8 * SW_BYTES;
                uint32_t ah[4];
                ah[0] = lds32(smem, OFF2_A + r0 + wb);
                ah[1] = lds32(smem, OFF2_A + r8 + wb);
                ah[2] = lds32(smem, OFF2_A + r0 + wb + 16);
                ah[3] = lds32(smem, OFF2_A + r8 + wb + 16);
#pragma unroll
                for (int ni = 0; ni < 8; ni++) mma16816h(acc[mi][ni], ah, bh[ni]);
            }
        }
    }

#pragma unroll
    for (int mi = 0; mi < 4; mi++) {
#pragma unroll
        for (int rr = 0; rr < 2; rr++) {
            const int row = wrow + mi * 16 + g + rr * 8;
            const size_t rbase = (row0 + row) * H_;
#pragma unroll
            for (int ni = 0; ni < 8; ni++) {
                const int col = wcol + ni * 8 + c * 2;
                float z0 = lrelu(acc[mi][ni][rr * 2 + 0] + c0[col]);
                float z1 = lrelu(acc[mi][ni][rr * 2 + 1] + c0[col + 1]);
                store2h(g_h2f, rbase + col, z0, z1);
            }
        }
    }
}

// ===========================================================================
// Stage 3 (fp16 single HMMA): fk = h2 @ W3 + b3 fused with contraction
// Grid (NTILES, B). Warp tile 64 rows x 32 cols.
// ===========================================================================
__global__ __launch_bounds__(256, 1)
void k_stage3(const float* __restrict__ x, const float* __restrict__ b3) {
    extern __shared__ char smem[];
    const int t = threadIdx.x, w = t >> 5, lane = t & 31;
    const int i0 = blockIdx.x * TI, b = blockIdx.y;

    float* sx   = (float*)(smem + OFF3_X);
    float* sred = (float*)(smem + OFF3_RED);

    if (t < TI) {
        const float* xp = x + ((size_t)b * N_ + i0 + t) * 3;
        sx[t * 4 + 0] = xp[0]; sx[t * 4 + 1] = xp[1]; sx[t * 4 + 2] = xp[2];
    }

    const int wrow = (w & 1) * 64;
    const int wcol = (w >> 1) * 32;
    const int g = lane >> 2;
    const int c = lane & 3;

    float acc[4][4][4];
#pragma unroll
    for (int mi = 0; mi < 4; mi++)
#pragma unroll
        for (int ni = 0; ni < 4; ni++)
#pragma unroll
            for (int e = 0; e < 4; e++) acc[mi][ni][e] = 0.f;

    const size_t row0 = (size_t)b * N_ + i0;

    for (int ch = 0; ch < 4; ch++) {
        const int k0 = ch * KC;
        __syncthreads();
#pragma unroll
        for (int m = 0; m < 4; m++) {
            const int q = t + m * 256;
            const int row = q >> 3, seg = q & 7;
            *(uint4*)(smem + OFF3_A + row * SW_BYTES + seg * 16) =
                *(const uint4*)(g_h2f + (row0 + row) * H_ + k0 + seg * 8);
        }
#pragma unroll
        for (int m = 0; m < 4; m++) {
            const int q = t + m * 256;
            const int row = q >> 3, seg = q & 7;
            *(uint4*)(smem + OFF3_W + row * SW_BYTES + seg * 16) =
                *(const uint4*)(g_W3f + (size_t)row * H_ + k0 + seg * 8);
        }
        __syncthreads();

#pragma unroll
        for (int k16 = 0; k16 < 4; k16++) {
            const int wb = (k16 * 8 + c) * 4;
            uint32_t bh[4][2];
#pragma unroll
            for (int ni = 0; ni < 4; ni++) {
                const int rb = (wcol + ni * 8 + g) * SW_BYTES;
                bh[ni][0] = lds32(smem, OFF3_W + rb + wb);
                bh[ni][1] = lds32(smem, OFF3_W + rb + wb + 16);
            }
#pragma unroll
            for (int mi = 0; mi < 4; mi++) {
                const int r0 = (wrow + mi * 16 + g) * SW_BYTES;
                const int r8 = r0 + 8 * SW_BYTES;
                uint32_t ah[4];
                ah[0] = lds32(smem, OFF3_A + r0 + wb);
                ah[1] = lds32(smem, OFF3_A + r8 + wb);
                ah[2] = lds32(smem, OFF3_A + r0 + wb + 16);
                ah[3] = lds32(smem, OFF3_A + r8 + wb + 16);
#pragma unroll
                for (int ni = 0; ni < 4; ni++) mma16816h(acc[mi][ni], ah, bh[ni]);
            }
        }
    }

    float b3c[8];
#pragma unroll
    for (int ni = 0; ni < 4; ni++)
#pragma unroll
        for (int e = 0; e < 2; e++)
            b3c[ni * 2 + e] = b3[wcol + ni * 8 + c * 2 + e];

    float po[8][3];
#pragma unroll
    for (int k = 0; k < 8; k++) { po[k][0] = 0.f; po[k][1] = 0.f; po[k][2] = 0.f; }

#pragma unroll
    for (int mi = 0; mi < 4; mi++) {
#pragma unroll
        for (int rr = 0; rr < 2; rr++) {
            const int row = wrow + mi * 16 + g + rr * 8;
            const float x0 = sx[row * 4 + 0];
            const float x1 = sx[row * 4 + 1];
            const float x2 = sx[row * 4 + 2];
#pragma unroll
            for (int ni = 0; ni < 4; ni++) {
#pragma unroll
                for (int e = 0; e < 2; e++) {
                    const float f = acc[mi][ni][rr * 2 + e] + b3c[ni * 2 + e];
                    po[ni * 2 + e][0] = fmaf(f, x0, po[ni * 2 + e][0]);
                    po[ni * 2 + e][1] = fmaf(f, x1, po[ni * 2 + e][1]);
                    po[ni * 2 + e][2] = fmaf(f, x2, po[ni * 2 + e][2]);
                }
            }
        }
    }
#pragma unroll
    for (int k = 0; k < 8; k++)
#pragma unroll
        for (int d = 0; d < 3; d++) {
            po[k][d] += __shfl_down_sync(0xffffffffu, po[k][d], 16);
            po[k][d] += __shfl_down_sync(0xffffffffu, po[k][d], 8);
            po[k][d] += __shfl_down_sync(0xffffffffu, po[k][d], 4);
        }
    if (lane < 4) {
#pragma unroll
        for (int k = 0; k < 8; k++)
#pragma unroll
            for (int d = 0; d < 3; d++)
                sred[((w * 4 + lane) * 8 + k) * 3 + d] = po[k][d];
    }
    __syncthreads();

    if (t < KOUT_) {
        const int o = t;
        const int w0 = (o >> 5) * 2;
        const int cc = (o & 7) >> 1;
        const int kk = ((o >> 3) & 3) * 2 + (o & 1);
        float s[3];
#pragma unroll
        for (int d = 0; d < 3; d++)
            s[d] = sred[(((w0)     * 4 + cc) * 8 + kk) * 3 + d]
                 + sred[(((w0 + 1) * 4 + cc) * 8 + kk) * 3 + d];
        const size_t base = (((size_t)b * NTILES + blockIdx.x) * KOUT_ + o) * 3;
        g_part[base + 0] = s[0]; g_part[base + 1] = s[1]; g_part[base + 2] = s[2];
    }
}

// ===========================================================================
// Stage 4: reduce tiles
// ===========================================================================
__global__ void k_reduce(float* __restrict__ out) {
    int t = blockIdx.x * blockDim.x + threadIdx.x;
    if (t >= B_ * KOUT_ * 3) return;
    int b = t / (KOUT_ * 3), rem = t % (KOUT_ * 3);
    float s = 0.f;
#pragma unroll
    for (int tile = 0; tile < NTILES; tile++)
        s += g_part[((size_t)b * NTILES + tile) * KOUT_ * 3 + rem];
    out[t] = s * (1.0f / N_);
}

// ===========================================================================
extern "C" void kernel_launch(void* const* d_in, const int* in_sizes, int n_in,
                              void* d_out, int out_size) {
    const float* x     = (const float*)d_in[0];
    const float* u     = (const float*)d_in[1];
    const float* basis = (const float*)d_in[2];
    const float* W1    = (const float*)d_in[3];
    const float* b1    = (const float*)d_in[4];
    const float* W2    = (const float*)d_in[5];
    const float* b2    = (const float*)d_in[6];
    const float* W3    = (const float*)d_in[7];
    const float* b3    = (const float*)d_in[8];
    float* out = (float*)d_out;

    cudaFuncSetAttribute(k_stage1, cudaFuncAttributeMaxDynamicSharedMemorySize, SMEM_SZ1);
    cudaFuncSetAttribute(k_stage2, cudaFuncAttributeMaxDynamicSharedMemorySize, SMEM_SZ2);
    cudaFuncSetAttribute(k_stage3, cudaFuncAttributeMaxDynamicSharedMemorySize, SMEM_SZ3);

    __half *dW1f, *dW2f, *dW3f;
    cudaGetSymbolAddress((void**)&dW1f, g_W1f);
    cudaGetSymbolAddress((void**)&dW2f, g_W2f);
    cudaGetSymbolAddress((void**)&dW3f, g_W3f);

    k_prep_f16<<<dim3(N_ / 32, H_ / 32), dim3(32, 8)>>>(W1 + 7 * H_, dW1f, N_, H_);
    k_prep_f16<<<dim3(H_ / 32, H_ / 32), dim3(32, 8)>>>(W2, dW2f, H_, H_);
    k_prep_f16<<<dim3(H_ / 32, KOUT_ / 32), dim3(32, 8)>>>(W3, dW3f, H_, KOUT_);

    k_dots<<<dim3(NT64, NT64, B_), 256>>>(x);
    k_stage1<<<dim3(NTILES, B_), 256, SMEM_SZ1>>>(x, u, basis, W1, b1);
    k_stage2<<<(B_ * N_) / TI, 256, SMEM_SZ2>>>(b2);
    k_stage3<<<dim3(NTILES, B_), 256, SMEM_SZ3>>>(x, b3);
    k_reduce<<<(B_ * KOUT_ * 3 + 255) / 256, 256>>>(out);
}